// round 11
// baseline (speedup 1.0000x reference)
#include <cuda_runtime.h>
#include <cstdint>

#define DIM 4096
#define NTHREADS 256
#define GRID 1036   // 148 SMs * 7 resident CTAs (16KB smem/CTA) -> single wave

#define CP_ASYNC16(dst_u32, src_ptr) \
    asm volatile("cp.async.cg.shared.global [%0], [%1], 16;" \
                 :: "r"(dst_u32), "l"(src_ptr) : "memory")
#define CP_COMMIT()  asm volatile("cp.async.commit_group;" ::: "memory")
#define CP_WAIT0()   asm volatile("cp.async.wait_group 0;" ::: "memory")

// Persistent-CTA FWHT-4096, SINGLE-buffer cp.async pipeline, 3 barriers/row.
// Buffer layout globally swizzled: phys(L) = L ^ (((L>>6)&7)<<2) (16B-chunk
// granular, applied at the cp.async destination). Per row:
//   pass1: dims e6..e9  (stride-64 gather, in-place)
//   pass2: dims e2..e5  (stride-4 gather, in-place)
//   pass3: dims e0,e1,e10,e11 (own float4 chunks -> registers)
// The pass-3 read addresses EQUAL the prefetch write addresses per thread,
// so the next row's cp.async can issue right after the own-chunk LDS with no
// trailing barrier and no second buffer.
__global__ void __launch_bounds__(NTHREADS, 7)
fwht4096_kernel(const float* __restrict__ x, float* __restrict__ out, int rows)
{
    __shared__ float sm[DIM];

    const int t = threadIdx.x;
    // swizzled float4 chunk base: (4t) ^ (((t>>4)&7)<<2)
    const int wb = (4 * t) ^ (((t >> 4) & 7) << 2);
    // pass-1 (stride-64) base
    const int base2 = (t & 63) + 1024 * (t >> 6);
    // pass-2 (stride-4) swizzled base
    const int P = ((t & 3) + 64 * ((t >> 2) & 15) + 1024 * (t >> 6))
                ^ (((t >> 2) & 7) << 2);
    // byte address of this thread's first smem chunk
    const uint32_t sb0 = (uint32_t)__cvta_generic_to_shared(&sm[wb]);

    const int row0 = blockIdx.x;

    // prologue: prefetch first row (swizzled layout)
    {
        const float* src = x + (size_t)row0 * DIM + 4 * t;
        #pragma unroll
        for (int c = 0; c < 4; ++c)
            CP_ASYNC16(sb0 + 4096u * c, src + 1024 * c);
        CP_COMMIT();
    }

    for (int row = row0; row < rows; row += GRID) {
        CP_WAIT0();
        __syncthreads();                       // row data visible to all

        float v[16];

        // ---- pass 1: dims e6..e9 (stride-64 gather, swizzled, in-place) ----
        #pragma unroll
        for (int m = 0; m < 16; ++m)
            v[m] = sm[(base2 ^ (4 * (m & 7))) + 64 * m];
        #pragma unroll
        for (int s = 0; s < 4; ++s) {
            const int h = 1 << s;
            #pragma unroll
            for (int j = 0; j < 16; ++j) {
                if ((j & h) == 0) {
                    float a = v[j], b = v[j + h];
                    v[j] = a + b;  v[j + h] = a - b;
                }
            }
        }
        #pragma unroll
        for (int m = 0; m < 16; ++m)
            sm[(base2 ^ (4 * (m & 7))) + 64 * m] = v[m];
        __syncthreads();

        // ---- pass 2: dims e2..e5 (stride-4 gather, swizzled, in-place) ----
        #pragma unroll
        for (int n = 0; n < 16; ++n) v[n] = sm[P ^ (4 * n)];
        #pragma unroll
        for (int s = 0; s < 4; ++s) {
            const int h = 1 << s;
            #pragma unroll
            for (int j = 0; j < 16; ++j) {
                if ((j & h) == 0) {
                    float a = v[j], b = v[j + h];
                    v[j] = a + b;  v[j + h] = a - b;
                }
            }
        }
        #pragma unroll
        for (int n = 0; n < 16; ++n) sm[P ^ (4 * n)] = v[n];
        __syncthreads();

        // ---- pass 3: own float4 chunks -> registers ----
        #pragma unroll
        for (int c = 0; c < 4; ++c) {
            float4 a = *reinterpret_cast<const float4*>(&sm[wb + 1024 * c]);
            v[4*c+0] = a.x; v[4*c+1] = a.y; v[4*c+2] = a.z; v[4*c+3] = a.w;
        }

        // prefetch next row into the SAME chunks (per-thread aliased with the
        // reads above: disjoint across threads, ordered within the thread; the
        // "memory" clobber keeps the LDS before the cp.async in issue order,
        // and the async smem-write lands ~global-latency later).
        {
            const int nrow = row + GRID;
            const float* src = x + (size_t)(nrow < rows ? nrow : row) * DIM + 4 * t;
            #pragma unroll
            for (int c = 0; c < 4; ++c)
                CP_ASYNC16(sb0 + 4096u * c, src + 1024 * c);
            CP_COMMIT();
        }

        // FWHT16 over dims e0,e1,e10,e11
        #pragma unroll
        for (int s = 0; s < 4; ++s) {
            const int h = 1 << s;
            #pragma unroll
            for (int j = 0; j < 16; ++j) {
                if ((j & h) == 0) {
                    float a = v[j], b = v[j + h];
                    v[j] = a + b;  v[j + h] = a - b;
                }
            }
        }

        // ---- scale (exact 1/64) + coalesced float4 stores ----
        const float SCALE = 0.015625f;
        float* __restrict__ po = out + (size_t)row * DIM + 4 * t;
        #pragma unroll
        for (int c = 0; c < 4; ++c) {
            float4 q = make_float4(v[4*c+0] * SCALE, v[4*c+1] * SCALE,
                                   v[4*c+2] * SCALE, v[4*c+3] * SCALE);
            *reinterpret_cast<float4*>(&po[1024 * c]) = q;
        }
    }
}

extern "C" void kernel_launch(void* const* d_in, const int* in_sizes, int n_in,
                              void* d_out, int out_size)
{
    const float* x = (const float*)d_in[0];
    float* out = (float*)d_out;
    const int rows = in_sizes[0] / DIM;   // 8192
    fwht4096_kernel<<<GRID, NTHREADS>>>(x, out, rows);
}

// round 12
// speedup vs baseline: 1.0449x; 1.0449x over previous
#include <cuda_runtime.h>
#include <cstdint>

#define DIM 4096
#define NTHREADS 256

#define CP_ASYNC16(dst_u32, src_ptr) \
    asm volatile("cp.async.cg.shared.global [%0], [%1], 16;" \
                 :: "r"(dst_u32), "l"(src_ptr) : "memory")
#define CP_COMMIT()  asm volatile("cp.async.commit_group;" ::: "memory")
#define CP_WAIT0()   asm volatile("cp.async.wait_group 0;" ::: "memory")

// FWHT-4096, TWO rows per CTA, non-persistent. 3 barriers per 2 rows.
// Buffer layout globally swizzled: phys(L) = L ^ (((L>>6)&7)<<2) (16B-chunk
// granular, applied at the cp.async destination). Per row:
//   pass1: dims e6..e9  (stride-64 gather, in-place, conflict-free)
//   pass2: dims e2..e5  (stride-4 gather via P^4n, in-place, conflict-free)
//   pass3: dims e0,e1,e10,e11 (own float4 chunks -> regs -> scale -> STG.128)
// Rows A and B are processed back-to-back inside each phase: independent
// dependency chains between barriers, half the barrier count per element.
__global__ void __launch_bounds__(NTHREADS, 7)
fwht4096_kernel(const float* __restrict__ x, float* __restrict__ out)
{
    __shared__ float sm[2][DIM];

    const int t = threadIdx.x;
    // swizzled float4 chunk base: (4t) ^ (((t>>4)&7)<<2)
    const int wb = (4 * t) ^ (((t >> 4) & 7) << 2);
    // pass-1 (stride-64) base
    const int base2 = (t & 63) + 1024 * (t >> 6);
    // pass-2 (stride-4) swizzled base
    const int P = ((t & 3) + 64 * ((t >> 2) & 15) + 1024 * (t >> 6))
                ^ (((t >> 2) & 7) << 2);

    const size_t row0 = (size_t)blockIdx.x * 2;

    // ---- load both rows via cp.async (no load registers, MLP=8) ----
    #pragma unroll
    for (int r = 0; r < 2; ++r) {
        const float* src = x + (row0 + r) * DIM + 4 * t;
        const uint32_t sb =
            (uint32_t)__cvta_generic_to_shared(&sm[r][wb]);
        #pragma unroll
        for (int c = 0; c < 4; ++c)
            CP_ASYNC16(sb + 4096u * c, src + 1024 * c);
    }
    CP_COMMIT();
    CP_WAIT0();
    __syncthreads();

    // ---- pass 1: dims e6..e9, rows A then B ----
    #pragma unroll
    for (int r = 0; r < 2; ++r) {
        float v[16];
        #pragma unroll
        for (int m = 0; m < 16; ++m)
            v[m] = sm[r][(base2 ^ (4 * (m & 7))) + 64 * m];
        #pragma unroll
        for (int s = 0; s < 4; ++s) {
            const int h = 1 << s;
            #pragma unroll
            for (int j = 0; j < 16; ++j) {
                if ((j & h) == 0) {
                    float a = v[j], b = v[j + h];
                    v[j] = a + b;  v[j + h] = a - b;
                }
            }
        }
        #pragma unroll
        for (int m = 0; m < 16; ++m)
            sm[r][(base2 ^ (4 * (m & 7))) + 64 * m] = v[m];
    }
    __syncthreads();

    // ---- pass 2: dims e2..e5, rows A then B ----
    #pragma unroll
    for (int r = 0; r < 2; ++r) {
        float v[16];
        #pragma unroll
        for (int n = 0; n < 16; ++n) v[n] = sm[r][P ^ (4 * n)];
        #pragma unroll
        for (int s = 0; s < 4; ++s) {
            const int h = 1 << s;
            #pragma unroll
            for (int j = 0; j < 16; ++j) {
                if ((j & h) == 0) {
                    float a = v[j], b = v[j + h];
                    v[j] = a + b;  v[j + h] = a - b;
                }
            }
        }
        #pragma unroll
        for (int n = 0; n < 16; ++n) sm[r][P ^ (4 * n)] = v[n];
    }
    __syncthreads();

    // ---- pass 3: dims e0,e1,e10,e11 + scale + vectorized store ----
    const float SCALE = 0.015625f;   // exact 1/64
    #pragma unroll
    for (int r = 0; r < 2; ++r) {
        float v[16];
        #pragma unroll
        for (int c = 0; c < 4; ++c) {
            float4 a = *reinterpret_cast<const float4*>(&sm[r][wb + 1024 * c]);
            v[4*c+0] = a.x; v[4*c+1] = a.y; v[4*c+2] = a.z; v[4*c+3] = a.w;
        }
        #pragma unroll
        for (int s = 0; s < 4; ++s) {
            const int h = 1 << s;
            #pragma unroll
            for (int j = 0; j < 16; ++j) {
                if ((j & h) == 0) {
                    float a = v[j], b = v[j + h];
                    v[j] = a + b;  v[j + h] = a - b;
                }
            }
        }
        float* __restrict__ po = out + (row0 + r) * DIM + 4 * t;
        #pragma unroll
        for (int c = 0; c < 4; ++c) {
            float4 q = make_float4(v[4*c+0] * SCALE, v[4*c+1] * SCALE,
                                   v[4*c+2] * SCALE, v[4*c+3] * SCALE);
            *reinterpret_cast<float4*>(&po[1024 * c]) = q;
        }
    }
}

extern "C" void kernel_launch(void* const* d_in, const int* in_sizes, int n_in,
                              void* d_out, int out_size)
{
    const float* x = (const float*)d_in[0];
    float* out = (float*)d_out;
    const int rows = in_sizes[0] / DIM;   // 8192
    fwht4096_kernel<<<rows / 2, NTHREADS>>>(x, out);
}

// round 13
// speedup vs baseline: 1.0941x; 1.0471x over previous
#include <cuda_runtime.h>

#define DIM 4096
#define NTHREADS 256

// FWHT-4096, one CTA per row, zero shuffles, <=32 regs (8 CTAs/SM).
// Identical structure to the best kernel (R4), plus streaming cache hints:
// input is read once and output written once (268MB stream vs 126MB L2), so
// LDG.CS / STG.CS (evict-first) avoid useless L2 churn.
//   pass1: local FWHT16 over {e0,e1,e10,e11}  (float4 loads at i=4t+1024c)
//   ex1:   smem gather of {e2..e5} (stride-4), local FWHT16, in-place writeback
//          addresses: P ^ 4n with P = base1 ^ X  (base1 bits2-5 == 0)
//   ex2:   smem gather of {e6..e9} (stride-64), local FWHT16, scale, store
// Global swizzle phys = L ^ (((L>>6)&7)<<2): conflict-free everywhere.
__global__ void __launch_bounds__(NTHREADS, 8)
fwht4096_kernel(const float* __restrict__ x, float* __restrict__ out)
{
    __shared__ float sm[DIM];

    const int t = threadIdx.x;
    const long long row = blockIdx.x;
    const float* __restrict__ px = x + row * (long long)DIM + 4 * t;

    float v[16];
    #pragma unroll
    for (int c = 0; c < 4; ++c) {
        float4 a = __ldcs(reinterpret_cast<const float4*>(px + 1024 * c));
        v[4*c+0] = a.x; v[4*c+1] = a.y; v[4*c+2] = a.z; v[4*c+3] = a.w;
    }

    // ---- pass1: FWHT16 over v-index bits (dims e0,e1,e10,e11) ----
    #pragma unroll
    for (int s = 0; s < 4; ++s) {
        const int h = 1 << s;
        #pragma unroll
        for (int j = 0; j < 16; ++j) {
            if ((j & h) == 0) {
                float a = v[j], b = v[j + h];
                v[j]     = a + b;
                v[j + h] = a - b;
            }
        }
    }

    // ---- exchange 1 write: float4 at logical 4t+1024c, swizzled ----
    {
        const int wb = (4 * t) ^ (((t >> 4) & 7) << 2);
        #pragma unroll
        for (int c = 0; c < 4; ++c) {
            *reinterpret_cast<float4*>(&sm[wb + 1024 * c]) =
                make_float4(v[4*c+0], v[4*c+1], v[4*c+2], v[4*c+3]);
        }
    }
    __syncthreads();

    // ---- exchange 1: gather dims e2..e5 (stride-4 words), swizzled ----
    // logical L = (t&3) + 4n + 64*((t>>2)&15) + 1024*(t>>6)
    // phys     = P ^ 4n,  P = base1 ^ X  (base1 bits 2-5 are zero)
    const int base1 = (t & 3) + 64 * ((t >> 2) & 15) + 1024 * (t >> 6);
    const int P = base1 ^ (((t >> 2) & 7) << 2);
    #pragma unroll
    for (int n = 0; n < 16; ++n) v[n] = sm[P ^ (4 * n)];

    // FWHT16 over n (dims e2..e5)
    #pragma unroll
    for (int s = 0; s < 4; ++s) {
        const int h = 1 << s;
        #pragma unroll
        for (int j = 0; j < 16; ++j) {
            if ((j & h) == 0) {
                float a = v[j], b = v[j + h];
                v[j]     = a + b;
                v[j + h] = a - b;
            }
        }
    }

    // in-place writeback (per-thread-disjoint slots)
    #pragma unroll
    for (int n = 0; n < 16; ++n) sm[P ^ (4 * n)] = v[n];
    __syncthreads();

    // ---- exchange 2: gather dims e6..e9 (stride-64 words), swizzled ----
    // logical L = (t&63) + 64m + 1024*(t>>6); phys = (base2 ^ 4*(m&7)) + 64m
    const int base2 = (t & 63) + 1024 * (t >> 6);
    #pragma unroll
    for (int m = 0; m < 16; ++m) {
        v[m] = sm[(base2 ^ (4 * (m & 7))) + 64 * m];
    }

    // FWHT16 over m (dims e6..e9)
    #pragma unroll
    for (int s = 0; s < 4; ++s) {
        const int h = 1 << s;
        #pragma unroll
        for (int j = 0; j < 16; ++j) {
            if ((j & h) == 0) {
                float a = v[j], b = v[j + h];
                v[j]     = a + b;
                v[j + h] = a - b;
            }
        }
    }

    // ---- scale (exact 1/64) + coalesced streaming stores ----
    const float SCALE = 0.015625f;
    float* __restrict__ po = out + row * (long long)DIM + base2;
    #pragma unroll
    for (int m = 0; m < 16; ++m) {
        __stcs(&po[64 * m], v[m] * SCALE);
    }
}

extern "C" void kernel_launch(void* const* d_in, const int* in_sizes, int n_in,
                              void* d_out, int out_size)
{
    const float* x = (const float*)d_in[0];
    float* out = (float*)d_out;
    const int rows = in_sizes[0] / DIM;   // 8192
    fwht4096_kernel<<<rows, NTHREADS>>>(x, out);
}